// round 2
// baseline (speedup 1.0000x reference)
#include <cuda_runtime.h>

// IF spiking neuron forward:
//   x: [T=8, N=4194304] fp32 (flattened view of [T*B, C, H, W])
//   thresh: [1] fp32
//   out[t, n] = s * thr where recurrence:
//     mem = 0.5*thr; for t: m = mem + x[t,n]; s = (m >= thr); mem = m - s*thr
//
// Pure streaming kernel: 128 MiB read + 128 MiB write. Strategy: one thread
// owns 4 consecutive neurons (float4), front-batches all 8 timestep loads
// (MLP=8 x 128B) to hide DRAM latency, computes the recurrence in registers,
// stores 8 float4.

#define T_STEPS 8
#define N_NEURONS (256 / T_STEPS * 512 * 16 * 16)   // 4,194,304
#define N4 (N_NEURONS / 4)                           // 1,048,576 float4 per timestep

__global__ __launch_bounds__(256) void if_forward_kernel(
    const float4* __restrict__ x,
    const float* __restrict__ thresh,
    float4* __restrict__ out)
{
    const int i = blockIdx.x * blockDim.x + threadIdx.x;  // grid exactly covers N4
    const float thr = __ldg(thresh);

    // Front-batch all 8 timestep loads for this neuron group (MLP = 8).
    float4 xv[T_STEPS];
#pragma unroll
    for (int t = 0; t < T_STEPS; t++) {
        xv[t] = x[(size_t)t * N4 + i];
    }

    float m0 = 0.5f * thr, m1 = m0, m2 = m0, m3 = m0;

#pragma unroll
    for (int t = 0; t < T_STEPS; t++) {
        m0 += xv[t].x;
        m1 += xv[t].y;
        m2 += xv[t].z;
        m3 += xv[t].w;
        float4 sp;
        sp.x = (m0 >= thr) ? thr : 0.0f;
        sp.y = (m1 >= thr) ? thr : 0.0f;
        sp.z = (m2 >= thr) ? thr : 0.0f;
        sp.w = (m3 >= thr) ? thr : 0.0f;
        m0 -= sp.x;
        m1 -= sp.y;
        m2 -= sp.z;
        m3 -= sp.w;
        out[(size_t)t * N4 + i] = sp;
    }
}

extern "C" void kernel_launch(void* const* d_in, const int* in_sizes, int n_in,
                              void* d_out, int out_size) {
    const float4* x = (const float4*)d_in[0];
    const float* thresh = (const float*)d_in[1];
    float4* out = (float4*)d_out;

    const int threads = 256;
    const int blocks = N4 / threads;  // 4096, exact
    if_forward_kernel<<<blocks, threads>>>(x, thresh, out);
}

// round 3
// speedup vs baseline: 1.0360x; 1.0360x over previous
#include <cuda_runtime.h>

// IF spiking neuron forward (R3):
//   x: [T=8, N=4194304] fp32, thresh: [1] fp32
//   mem = 0.5*thr; per t: m = mem + x[t]; s = (m>=thr); out[t] = s*thr; mem = m - s*thr
//
// Pure 1:1 read/write stream (128 MiB each way). R3 changes vs R2:
//  - ITEMS=2 float4 groups per thread (16 front-batched LDG.128 -> 256B MLP/thread)
//  - __ldcs/__stcs streaming hints (zero-reuse data; avoid L2 thrash on 256MB set)

#define T_STEPS 8
#define N_NEURONS (256 / T_STEPS * 512 * 16 * 16)   // 4,194,304
#define N4 (N_NEURONS / 4)                           // 1,048,576 float4 per timestep
#define ITEMS 2
#define TPB 256

__global__ __launch_bounds__(TPB) void if_forward_kernel(
    const float4* __restrict__ x,
    const float* __restrict__ thresh,
    float4* __restrict__ out)
{
    const int base = blockIdx.x * (TPB * ITEMS) + threadIdx.x;  // grid exactly covers N4
    const float thr = __ldg(thresh);

    // Front-batch all T*ITEMS loads (MLP = 16 x 128B per warp-lane group).
    float4 xv[T_STEPS][ITEMS];
#pragma unroll
    for (int t = 0; t < T_STEPS; t++) {
#pragma unroll
        for (int j = 0; j < ITEMS; j++) {
            xv[t][j] = __ldcs(&x[(size_t)t * N4 + base + j * TPB]);
        }
    }

    float m[ITEMS][4];
#pragma unroll
    for (int j = 0; j < ITEMS; j++) {
        m[j][0] = m[j][1] = m[j][2] = m[j][3] = 0.5f * thr;
    }

#pragma unroll
    for (int t = 0; t < T_STEPS; t++) {
#pragma unroll
        for (int j = 0; j < ITEMS; j++) {
            m[j][0] += xv[t][j].x;
            m[j][1] += xv[t][j].y;
            m[j][2] += xv[t][j].z;
            m[j][3] += xv[t][j].w;
            float4 sp;
            sp.x = (m[j][0] >= thr) ? thr : 0.0f;
            sp.y = (m[j][1] >= thr) ? thr : 0.0f;
            sp.z = (m[j][2] >= thr) ? thr : 0.0f;
            sp.w = (m[j][3] >= thr) ? thr : 0.0f;
            m[j][0] -= sp.x;
            m[j][1] -= sp.y;
            m[j][2] -= sp.z;
            m[j][3] -= sp.w;
            __stcs(&out[(size_t)t * N4 + base + j * TPB], sp);
        }
    }
}

extern "C" void kernel_launch(void* const* d_in, const int* in_sizes, int n_in,
                              void* d_out, int out_size) {
    const float4* x = (const float4*)d_in[0];
    const float* thresh = (const float*)d_in[1];
    float4* out = (float4*)d_out;

    const int blocks = N4 / (TPB * ITEMS);  // 2048, exact
    if_forward_kernel<<<blocks, TPB>>>(x, thresh, out);
}